// round 5
// baseline (speedup 1.0000x reference)
#include <cuda_runtime.h>

#define NB 8
#define PP 2048
#define DD 64
#define EPSI 1e-3f
#define KK 1442.69504089f        /* 1000 * log2(e) */
#define EL2 6.9314718056e-4f     /* ln2 / 1000 */
#define NPb (NB*PP)
#define RPB 32                   /* rows per fused-iter block */
#define NCHUNK (PP/RPB)          /* 64 chunks per batch */

__device__ __align__(256) float g_C[(size_t)NB * PP * PP]; // 134 MB cost matrix
__device__ __align__(256) float g_An[NPb * DD];
__device__ __align__(256) float g_Bn[NPb * DD];
__device__ __align__(256) float g_rs[NPb];
__device__ __align__(256) float g_cs[NPb];
__device__ __align__(256) float g_lmu[NPb];
__device__ __align__(256) float g_lnu[NPb];
__device__ __align__(256) float g_u[NPb];
__device__ __align__(256) float g_v[NPb];
__device__ __align__(256) float g_pm[NB * NCHUNK * PP];   // col partial max (log2)
__device__ __align__(256) float g_ps[NB * NCHUNK * PP];   // col partial sum
__device__ float g_errsum[16];
__device__ int g_flag;

// ---------------- block sum reduction (256 threads) ------------------------
__device__ __forceinline__ float block_sum256(float v, float* red) {
    __syncthreads();
    #pragma unroll
    for (int off = 16; off; off >>= 1) v += __shfl_xor_sync(0xffffffffu, v, off);
    int w = threadIdx.x >> 5, l = threadIdx.x & 31;
    if (l == 0) red[w] = v;
    __syncthreads();
    if (threadIdx.x < 32) {
        float x = (l < 8) ? red[l] : 0.0f;
        #pragma unroll
        for (int off = 4; off; off >>= 1) x += __shfl_xor_sync(0xffffffffu, x, off);
        if (l == 0) red[32] = x;
    }
    __syncthreads();
    return red[32];
}

// ---------------- prep: normalize inputs, zero state -----------------------
__global__ __launch_bounds__(256) void k_prep(const float* __restrict__ a,
                                              const float* __restrict__ b,
                                              float* __restrict__ out) {
    int idx = blockIdx.x * 256 + threadIdx.x;          // 0..16383
    {
        const float4* s = (const float4*)(a + (size_t)idx * DD);
        float nrm = 0.0f;
        #pragma unroll
        for (int q = 0; q < 16; q++) {
            float4 t = s[q];
            nrm += t.x * t.x + t.y * t.y + t.z * t.z + t.w * t.w;
        }
        float sc = 1.0f / fmaxf(sqrtf(nrm), 1e-12f);
        float4* d = (float4*)(g_An + (size_t)idx * DD);
        #pragma unroll
        for (int q = 0; q < 16; q++) {
            float4 t = s[q];
            t.x *= sc; t.y *= sc; t.z *= sc; t.w *= sc;
            d[q] = t;
        }
    }
    {
        const float4* s = (const float4*)(b + (size_t)idx * DD);
        float nrm = 0.0f;
        #pragma unroll
        for (int q = 0; q < 16; q++) {
            float4 t = s[q];
            nrm += t.x * t.x + t.y * t.y + t.z * t.z + t.w * t.w;
        }
        float sc = 1.0f / fmaxf(sqrtf(nrm), 1e-12f);
        float4* d = (float4*)(g_Bn + (size_t)idx * DD);
        #pragma unroll
        for (int q = 0; q < 16; q++) {
            float4 t = s[q];
            t.x *= sc; t.y *= sc; t.z *= sc; t.w *= sc;
            d[q] = t;
        }
    }
    g_u[idx] = 0.0f; g_v[idx] = 0.0f; g_rs[idx] = 0.0f; g_cs[idx] = 0.0f;
    if (idx < NB) out[idx] = 0.0f;
    if (idx < 16) g_errsum[idx] = 0.0f;
    if (idx == 0) g_flag = 0;
}

// ---------------- GEMM: C = 1 - Ahat . Bhat^T, fused S row/col sums --------
__global__ __launch_bounds__(256) void k_gemm() {
    __shared__ float As[128][33];
    __shared__ float Bs[32][132];
    int b = blockIdx.z;
    int row0 = blockIdx.y * 128, col0 = blockIdx.x * 128;
    const float* Ab = g_An + (size_t)b * PP * DD;
    const float* Bb = g_Bn + (size_t)b * PP * DD;
    int t = threadIdx.x, tx = t & 15, ty = t >> 4;

    unsigned long long acc[8][4];
    #pragma unroll
    for (int i = 0; i < 8; i++)
        #pragma unroll
        for (int j = 0; j < 4; j++) acc[i][j] = 0ULL;

    #pragma unroll
    for (int kp = 0; kp < 2; kp++) {
        __syncthreads();
        int kq = t & 7, rq = t >> 3;
        #pragma unroll
        for (int p = 0; p < 4; p++) {
            int r = p * 32 + rq;
            float4 v = *(const float4*)(Ab + (size_t)(row0 + r) * DD + kp * 32 + kq * 4);
            As[r][kq * 4 + 0] = v.x; As[r][kq * 4 + 1] = v.y;
            As[r][kq * 4 + 2] = v.z; As[r][kq * 4 + 3] = v.w;
            float4 w = *(const float4*)(Bb + (size_t)(col0 + r) * DD + kp * 32 + kq * 4);
            Bs[kq * 4 + 0][r] = w.x; Bs[kq * 4 + 1][r] = w.y;
            Bs[kq * 4 + 2][r] = w.z; Bs[kq * 4 + 3][r] = w.w;
        }
        __syncthreads();
        #pragma unroll 4
        for (int k = 0; k < 32; k++) {
            union { float4 f; unsigned long long u[2]; } b0, b1;
            b0.f = *(const float4*)&Bs[k][tx * 4];
            b1.f = *(const float4*)&Bs[k][64 + tx * 4];
            #pragma unroll
            for (int i = 0; i < 8; i++) {
                unsigned int ai = __float_as_uint(As[ty * 8 + i][k]);
                unsigned long long a2;
                asm("mov.b64 %0, {%1, %1};" : "=l"(a2) : "r"(ai));
                asm("fma.rn.f32x2 %0, %1, %2, %0;" : "+l"(acc[i][0]) : "l"(a2), "l"(b0.u[0]));
                asm("fma.rn.f32x2 %0, %1, %2, %0;" : "+l"(acc[i][1]) : "l"(a2), "l"(b0.u[1]));
                asm("fma.rn.f32x2 %0, %1, %2, %0;" : "+l"(acc[i][2]) : "l"(a2), "l"(b1.u[0]));
                asm("fma.rn.f32x2 %0, %1, %2, %0;" : "+l"(acc[i][3]) : "l"(a2), "l"(b1.u[1]));
            }
        }
    }
    __syncthreads();

    float rs[8], cs8[8];
    #pragma unroll
    for (int j = 0; j < 8; j++) cs8[j] = 0.0f;
    #pragma unroll
    for (int i = 0; i < 8; i++) {
        float vals[8];
        #pragma unroll
        for (int jp = 0; jp < 4; jp++) {
            union { unsigned long long u; float2 f; } cv; cv.u = acc[i][jp];
            vals[jp * 2 + 0] = cv.f.x;
            vals[jp * 2 + 1] = cv.f.y;
        }
        size_t base = ((size_t)b * PP + row0 + ty * 8 + i) * (size_t)PP + col0;
        *(float4*)(g_C + base + tx * 4) =
            make_float4(1.0f - vals[0], 1.0f - vals[1], 1.0f - vals[2], 1.0f - vals[3]);
        *(float4*)(g_C + base + 64 + tx * 4) =
            make_float4(1.0f - vals[4], 1.0f - vals[5], 1.0f - vals[6], 1.0f - vals[7]);
        float rsum = 0.0f;
        #pragma unroll
        for (int j = 0; j < 8; j++) { rsum += vals[j]; cs8[j] += vals[j]; }
        rs[i] = rsum;
    }
    float* red = (float*)As;
    #pragma unroll
    for (int i = 0; i < 8; i++) red[(ty * 8 + i) * 16 + tx] = rs[i];
    __syncthreads();
    if (t < 128) {
        float s = 0.0f;
        #pragma unroll
        for (int q = 0; q < 16; q++) s += red[t * 16 + q];
        atomicAdd(&g_rs[b * PP + row0 + t], s);
    }
    __syncthreads();
    #pragma unroll
    for (int j = 0; j < 8; j++) {
        int cc = (j < 4) ? (tx * 4 + j) : (64 + tx * 4 + (j - 4));
        red[cc * 16 + ty] = cs8[j];
    }
    __syncthreads();
    if (t < 128) {
        float s = 0.0f;
        #pragma unroll
        for (int q = 0; q < 16; q++) s += red[t * 16 + q];
        atomicAdd(&g_cs[b * PP + col0 + t], s);
    }
}

// ---------------- weights -> log(mu+1e-8) ----------------------------------
__device__ __forceinline__ void wproc(const float* __restrict__ sum,
                                      float* __restrict__ out, float* red, int t) {
    float raw[8], s = 0.0f;
    #pragma unroll
    for (int q = 0; q < 8; q++) {
        raw[q] = sum[t + 256 * q] * (1.0f / PP);
        s += fabsf(raw[q]);
    }
    s = block_sum256(s, red);
    float inv1 = 1.0f / fmaxf(s, 1e-12f);
    float c[8]; float s2 = 0.0f;
    #pragma unroll
    for (int q = 0; q < 8; q++) { c[q] = fmaxf(raw[q] * inv1, 0.0f); s2 += fabsf(c[q]); }
    s2 = block_sum256(s2, red);
    float inv2 = 1.0f / fmaxf(s2, 1e-12f);
    #pragma unroll
    for (int q = 0; q < 8; q++) out[t + 256 * q] = logf(c[q] * inv2 + 1e-8f);
}

__global__ __launch_bounds__(256) void k_weights() {
    __shared__ float red[40];
    int b = blockIdx.x, t = threadIdx.x;
    wproc(g_rs + b * PP, g_lmu + b * PP, red, t);
    wproc(g_cs + b * PP, g_lnu + b * PP, red, t);
}

// ---- FUSED iteration: one sweep over a 32-row chunk computes u for each
// row (block lse) AND accumulates per-column online-lse partials with the
// new u. C read once per iteration.
__global__ __launch_bounds__(256) void k_iter(int it) {
    if (g_flag) return;
    __shared__ float redM[8], redS[8];
    __shared__ float lmu_s[RPB];
    int t = threadIdx.x, l = t & 31, w = t >> 5;
    int b = blockIdx.x >> 6;             // 512 blocks = 8 b x 64 chunks
    int chunk = blockIdx.x & 63;
    int rowbase = (b << 11) + (chunk << 5);
    if (t < RPB) lmu_s[t] = g_lmu[rowbase + t];
    // thread's 8 fixed columns: 4t..4t+3 and 1024+4t..+3
    float4 vk0 = *(const float4*)(g_v + (b << 11) + 4 * t);
    float4 vk1 = *(const float4*)(g_v + (b << 11) + 1024 + 4 * t);
    float vk[8] = { vk0.x * KK, vk0.y * KK, vk0.z * KK, vk0.w * KK,
                    vk1.x * KK, vk1.y * KK, vk1.z * KK, vk1.w * KK };
    float cm[8], cs8[8];
    #pragma unroll
    for (int q = 0; q < 8; q++) { cm[q] = -3.0e38f; cs8[q] = 0.0f; }
    __syncthreads();

    const float* Crow = g_C + ((size_t)rowbase << 11);
    float4 cur0 = *(const float4*)(Crow + 4 * t);
    float4 cur1 = *(const float4*)(Crow + 1024 + 4 * t);
    float erracc = 0.0f;

    #pragma unroll 1
    for (int r = 0; r < RPB; r++) {
        float4 nx0, nx1;
        if (r + 1 < RPB) {
            nx0 = *(const float4*)(Crow + 2048 + 4 * t);
            nx1 = *(const float4*)(Crow + 2048 + 1024 + 4 * t);
        }
        float x[8];
        x[0] = fmaf(cur0.x, -KK, vk[0]); x[1] = fmaf(cur0.y, -KK, vk[1]);
        x[2] = fmaf(cur0.z, -KK, vk[2]); x[3] = fmaf(cur0.w, -KK, vk[3]);
        x[4] = fmaf(cur1.x, -KK, vk[4]); x[5] = fmaf(cur1.y, -KK, vk[5]);
        x[6] = fmaf(cur1.z, -KK, vk[6]); x[7] = fmaf(cur1.w, -KK, vk[7]);
        float lm = fmaxf(fmaxf(fmaxf(x[0], x[1]), fmaxf(x[2], x[3])),
                         fmaxf(fmaxf(x[4], x[5]), fmaxf(x[6], x[7])));
        #pragma unroll
        for (int off = 16; off; off >>= 1)
            lm = fmaxf(lm, __shfl_xor_sync(0xffffffffu, lm, off));
        if (l == 0) redM[w] = lm;
        __syncthreads();
        float M = fmaxf(fmaxf(fmaxf(redM[0], redM[1]), fmaxf(redM[2], redM[3])),
                        fmaxf(fmaxf(redM[4], redM[5]), fmaxf(redM[6], redM[7])));
        float s0 = exp2f(x[0] - M) + exp2f(x[4] - M);
        float s1 = exp2f(x[1] - M) + exp2f(x[5] - M);
        float s2 = exp2f(x[2] - M) + exp2f(x[6] - M);
        float s3 = exp2f(x[3] - M) + exp2f(x[7] - M);
        float s = (s0 + s1) + (s2 + s3);
        #pragma unroll
        for (int off = 16; off; off >>= 1) s += __shfl_xor_sync(0xffffffffu, s, off);
        if (l == 0) redS[w] = s;
        __syncthreads();
        float S = ((redS[0] + redS[1]) + (redS[2] + redS[3]))
                + ((redS[4] + redS[5]) + (redS[6] + redS[7]));
        float lse = M + __log2f(S);
        float un = EPSI * lmu_s[r] - EL2 * lse;       // natural units
        float uiK = un * KK;
        if (t == 0) {
            erracc += fabsf(un - g_u[rowbase + r]);
            g_u[rowbase + r] = un;
        }
        // col online update: y = x + (uiK - vk)
        #pragma unroll
        for (int q = 0; q < 8; q++) {
            float y = x[q] + (uiK - vk[q]);
            float mn = fmaxf(cm[q], y);
            cs8[q] = fmaf(cs8[q], exp2f(cm[q] - mn), exp2f(y - mn));
            cm[q] = mn;
        }
        cur0 = nx0; cur1 = nx1;
        Crow += 2048;
    }
    // write partials (coalesced float4)
    size_t pidx = ((size_t)blockIdx.x << 11);
    *(float4*)(g_pm + pidx + 4 * t)        = make_float4(cm[0], cm[1], cm[2], cm[3]);
    *(float4*)(g_pm + pidx + 1024 + 4 * t) = make_float4(cm[4], cm[5], cm[6], cm[7]);
    *(float4*)(g_ps + pidx + 4 * t)        = make_float4(cs8[0], cs8[1], cs8[2], cs8[3]);
    *(float4*)(g_ps + pidx + 1024 + 4 * t) = make_float4(cs8[4], cs8[5], cs8[6], cs8[7]);
    if (t == 0) atomicAdd(&g_errsum[it], erracc);
}

// ---- combine col partials -> v; set early-stop flag ------------------------
__global__ __launch_bounds__(256) void k_combine(int it) {
    if (g_flag) return;
    int t = blockIdx.x * 256 + threadIdx.x;     // 16384 = b*2048 + j
    int b = t >> 11, j = t & 2047;
    float M = -3.0e38f, S = 0.0f;
    #pragma unroll 4
    for (int ch = 0; ch < NCHUNK; ch++) {
        size_t pidx = ((size_t)((b << 6) + ch) << 11) + j;
        float m = g_pm[pidx];
        float s = g_ps[pidx];
        float mn = fmaxf(M, m);
        S = fmaf(S, exp2f(M - mn), s * exp2f(m - mn));
        M = mn;
    }
    g_v[t] = EPSI * g_lnu[t] - EL2 * (M + __log2f(S));
    if (t == 0) {
        // err = sum(|du|)/NB < 0.1  <=>  errsum < 0.8 (k_iter fully retired)
        if (g_errsum[it] < 0.1f * NB) g_flag = 1;
    }
}

// ---- final: out[b] = sum_ij exp((u+v-C)/eps)*C ; warp-pair per row --------
__global__ __launch_bounds__(256) void k_final(float* __restrict__ out) {
    __shared__ float vs[2048];          // v * KK
    __shared__ float srw[8];
    int t = threadIdx.x, l = t & 31, w = t >> 5;
    int b = blockIdx.x >> 9;
    const float4* vsrc = (const float4*)(g_v + (b << 11));
    #pragma unroll
    for (int q = 0; q < 2; q++) {
        float4 v4 = vsrc[t + q * 256];
        ((float4*)vs)[t + q * 256] = make_float4(v4.x * KK, v4.y * KK, v4.z * KK, v4.w * KK);
    }
    __syncthreads();
    int row4 = (blockIdx.x & 511) << 2;
    int bi = (b << 11) + row4 + (w >> 1);
    int half = w & 1;
    float uw = g_u[bi] * KK;
    const float* Crow = g_C + ((size_t)bi << 11) + (half << 10);
    const float* vh = vs + (half << 10);
    float s0 = 0.0f, s1 = 0.0f, s2 = 0.0f, s3 = 0.0f;
    #pragma unroll
    for (int k = 0; k < 8; k++) {
        float4 c = *(const float4*)(Crow + k * 128 + l * 4);
        float4 vv = *(const float4*)(vh + k * 128 + l * 4);
        s0 = fmaf(exp2f(fmaf(c.x, -KK, uw + vv.x)), c.x, s0);
        s1 = fmaf(exp2f(fmaf(c.y, -KK, uw + vv.y)), c.y, s1);
        s2 = fmaf(exp2f(fmaf(c.z, -KK, uw + vv.z)), c.z, s2);
        s3 = fmaf(exp2f(fmaf(c.w, -KK, uw + vv.w)), c.w, s3);
    }
    float s = (s0 + s1) + (s2 + s3);
    #pragma unroll
    for (int off = 16; off; off >>= 1) s += __shfl_xor_sync(0xffffffffu, s, off);
    if (l == 0) srw[w] = s;
    __syncthreads();
    if (t == 0) {
        float e = 0.0f;
        #pragma unroll
        for (int q = 0; q < 8; q++) e += srw[q];
        atomicAdd(&out[b], e);
    }
}

extern "C" void kernel_launch(void* const* d_in, const int* in_sizes, int n_in,
                              void* d_out, int out_size) {
    const float* a = (const float*)d_in[0];
    const float* b = (const float*)d_in[1];
    float* out = (float*)d_out;
    k_prep<<<64, 256>>>(a, b, out);
    dim3 gg(16, 16, NB);
    k_gemm<<<gg, 256>>>();
    k_weights<<<NB, 256>>>();
    for (int it = 0; it < 10; it++) {
        k_iter<<<512, 256>>>(it);
        k_combine<<<64, 256>>>(it);
    }
    k_final<<<4096, 256>>>(out);
}

// round 6
// speedup vs baseline: 1.2243x; 1.2243x over previous
#include <cuda_runtime.h>

#define NB 8
#define PP 2048
#define DD 64
#define EPSI 1e-3f
#define KK 1442.69504089f        /* 1000 * log2(e) */
#define EL2 6.9314718056e-4f     /* ln2 / 1000 */
#define NPb (NB*PP)

__device__ __align__(256) float g_C[(size_t)NB * PP * PP]; // 134 MB cost matrix
__device__ __align__(256) float g_An[NPb * DD];
__device__ __align__(256) float g_Bn[NPb * DD];
__device__ __align__(256) float g_rs[NPb];
__device__ __align__(256) float g_cs[NPb];
__device__ __align__(256) float g_lmu[NPb];
__device__ __align__(256) float g_lnu[NPb];
__device__ __align__(256) float g_u[NPb];
__device__ __align__(256) float g_v[NPb];
__device__ __align__(256) float g_pm[NB * 16 * PP];   // col partial max (log2 units)
__device__ __align__(256) float g_ps[NB * 16 * PP];   // col partial sum
__device__ float g_errsum[16];
__device__ int g_flag;

// ---------------- block sum reduction (256 threads) ------------------------
__device__ __forceinline__ float block_sum256(float v, float* red) {
    __syncthreads();
    #pragma unroll
    for (int off = 16; off; off >>= 1) v += __shfl_xor_sync(0xffffffffu, v, off);
    int w = threadIdx.x >> 5, l = threadIdx.x & 31;
    if (l == 0) red[w] = v;
    __syncthreads();
    if (threadIdx.x < 32) {
        float x = (l < 8) ? red[l] : 0.0f;
        #pragma unroll
        for (int off = 4; off; off >>= 1) x += __shfl_xor_sync(0xffffffffu, x, off);
        if (l == 0) red[32] = x;
    }
    __syncthreads();
    return red[32];
}

// ---------------- prep: normalize inputs, zero state -----------------------
__global__ __launch_bounds__(256) void k_prep(const float* __restrict__ a,
                                              const float* __restrict__ b,
                                              float* __restrict__ out) {
    int idx = blockIdx.x * 256 + threadIdx.x;          // 0..16383
    {
        const float4* s = (const float4*)(a + (size_t)idx * DD);
        float nrm = 0.0f;
        #pragma unroll
        for (int q = 0; q < 16; q++) {
            float4 t = s[q];
            nrm += t.x * t.x + t.y * t.y + t.z * t.z + t.w * t.w;
        }
        float sc = 1.0f / fmaxf(sqrtf(nrm), 1e-12f);
        float4* d = (float4*)(g_An + (size_t)idx * DD);
        #pragma unroll
        for (int q = 0; q < 16; q++) {
            float4 t = s[q];
            t.x *= sc; t.y *= sc; t.z *= sc; t.w *= sc;
            d[q] = t;
        }
    }
    {
        const float4* s = (const float4*)(b + (size_t)idx * DD);
        float nrm = 0.0f;
        #pragma unroll
        for (int q = 0; q < 16; q++) {
            float4 t = s[q];
            nrm += t.x * t.x + t.y * t.y + t.z * t.z + t.w * t.w;
        }
        float sc = 1.0f / fmaxf(sqrtf(nrm), 1e-12f);
        float4* d = (float4*)(g_Bn + (size_t)idx * DD);
        #pragma unroll
        for (int q = 0; q < 16; q++) {
            float4 t = s[q];
            t.x *= sc; t.y *= sc; t.z *= sc; t.w *= sc;
            d[q] = t;
        }
    }
    g_u[idx] = 0.0f; g_v[idx] = 0.0f; g_rs[idx] = 0.0f; g_cs[idx] = 0.0f;
    if (idx < NB) out[idx] = 0.0f;
    if (idx < 16) g_errsum[idx] = 0.0f;
    if (idx == 0) g_flag = 0;
}

// ---------------- GEMM: C = 1 - Ahat . Bhat^T, fused S row/col sums --------
__global__ __launch_bounds__(256) void k_gemm() {
    __shared__ float As[128][33];
    __shared__ float Bs[32][132];
    int b = blockIdx.z;
    int row0 = blockIdx.y * 128, col0 = blockIdx.x * 128;
    const float* Ab = g_An + (size_t)b * PP * DD;
    const float* Bb = g_Bn + (size_t)b * PP * DD;
    int t = threadIdx.x, tx = t & 15, ty = t >> 4;

    unsigned long long acc[8][4];
    #pragma unroll
    for (int i = 0; i < 8; i++)
        #pragma unroll
        for (int j = 0; j < 4; j++) acc[i][j] = 0ULL;

    #pragma unroll
    for (int kp = 0; kp < 2; kp++) {
        __syncthreads();
        int kq = t & 7, rq = t >> 3;
        #pragma unroll
        for (int p = 0; p < 4; p++) {
            int r = p * 32 + rq;
            float4 v = *(const float4*)(Ab + (size_t)(row0 + r) * DD + kp * 32 + kq * 4);
            As[r][kq * 4 + 0] = v.x; As[r][kq * 4 + 1] = v.y;
            As[r][kq * 4 + 2] = v.z; As[r][kq * 4 + 3] = v.w;
            float4 w = *(const float4*)(Bb + (size_t)(col0 + r) * DD + kp * 32 + kq * 4);
            Bs[kq * 4 + 0][r] = w.x; Bs[kq * 4 + 1][r] = w.y;
            Bs[kq * 4 + 2][r] = w.z; Bs[kq * 4 + 3][r] = w.w;
        }
        __syncthreads();
        #pragma unroll 4
        for (int k = 0; k < 32; k++) {
            union { float4 f; unsigned long long u[2]; } b0, b1;
            b0.f = *(const float4*)&Bs[k][tx * 4];
            b1.f = *(const float4*)&Bs[k][64 + tx * 4];
            #pragma unroll
            for (int i = 0; i < 8; i++) {
                unsigned int ai = __float_as_uint(As[ty * 8 + i][k]);
                unsigned long long a2;
                asm("mov.b64 %0, {%1, %1};" : "=l"(a2) : "r"(ai));
                asm("fma.rn.f32x2 %0, %1, %2, %0;" : "+l"(acc[i][0]) : "l"(a2), "l"(b0.u[0]));
                asm("fma.rn.f32x2 %0, %1, %2, %0;" : "+l"(acc[i][1]) : "l"(a2), "l"(b0.u[1]));
                asm("fma.rn.f32x2 %0, %1, %2, %0;" : "+l"(acc[i][2]) : "l"(a2), "l"(b1.u[0]));
                asm("fma.rn.f32x2 %0, %1, %2, %0;" : "+l"(acc[i][3]) : "l"(a2), "l"(b1.u[1]));
            }
        }
    }
    __syncthreads();

    float rs[8], cs8[8];
    #pragma unroll
    for (int j = 0; j < 8; j++) cs8[j] = 0.0f;
    #pragma unroll
    for (int i = 0; i < 8; i++) {
        float vals[8];
        #pragma unroll
        for (int jp = 0; jp < 4; jp++) {
            union { unsigned long long u; float2 f; } cv; cv.u = acc[i][jp];
            vals[jp * 2 + 0] = cv.f.x;
            vals[jp * 2 + 1] = cv.f.y;
        }
        size_t base = ((size_t)b * PP + row0 + ty * 8 + i) * (size_t)PP + col0;
        *(float4*)(g_C + base + tx * 4) =
            make_float4(1.0f - vals[0], 1.0f - vals[1], 1.0f - vals[2], 1.0f - vals[3]);
        *(float4*)(g_C + base + 64 + tx * 4) =
            make_float4(1.0f - vals[4], 1.0f - vals[5], 1.0f - vals[6], 1.0f - vals[7]);
        float rsum = 0.0f;
        #pragma unroll
        for (int j = 0; j < 8; j++) { rsum += vals[j]; cs8[j] += vals[j]; }
        rs[i] = rsum;
    }
    float* red = (float*)As;
    #pragma unroll
    for (int i = 0; i < 8; i++) red[(ty * 8 + i) * 16 + tx] = rs[i];
    __syncthreads();
    if (t < 128) {
        float s = 0.0f;
        #pragma unroll
        for (int q = 0; q < 16; q++) s += red[t * 16 + q];
        atomicAdd(&g_rs[b * PP + row0 + t], s);
    }
    __syncthreads();
    #pragma unroll
    for (int j = 0; j < 8; j++) {
        int cc = (j < 4) ? (tx * 4 + j) : (64 + tx * 4 + (j - 4));
        red[cc * 16 + ty] = cs8[j];
    }
    __syncthreads();
    if (t < 128) {
        float s = 0.0f;
        #pragma unroll
        for (int q = 0; q < 16; q++) s += red[t * 16 + q];
        atomicAdd(&g_cs[b * PP + col0 + t], s);
    }
}

// ---------------- weights -> log(mu+1e-8) ----------------------------------
__device__ __forceinline__ void wproc(const float* __restrict__ sum,
                                      float* __restrict__ out, float* red, int t) {
    float raw[8], s = 0.0f;
    #pragma unroll
    for (int q = 0; q < 8; q++) {
        raw[q] = sum[t + 256 * q] * (1.0f / PP);
        s += fabsf(raw[q]);
    }
    s = block_sum256(s, red);
    float inv1 = 1.0f / fmaxf(s, 1e-12f);
    float c[8]; float s2 = 0.0f;
    #pragma unroll
    for (int q = 0; q < 8; q++) { c[q] = fmaxf(raw[q] * inv1, 0.0f); s2 += fabsf(c[q]); }
    s2 = block_sum256(s2, red);
    float inv2 = 1.0f / fmaxf(s2, 1e-12f);
    #pragma unroll
    for (int q = 0; q < 8; q++) out[t + 256 * q] = logf(c[q] * inv2 + 1e-8f);
}

__global__ __launch_bounds__(256) void k_weights() {
    __shared__ float red[40];
    int b = blockIdx.x, t = threadIdx.x;
    wproc(g_rs + b * PP, g_lmu + b * PP, red, t);
    wproc(g_cs + b * PP, g_lnu + b * PP, red, t);
}

// ---- row pass (REVERSE sweep): warp-pair per row, two-loop lse ------------
// serpentine: previous pass (gemm/col) ended at high addresses -> start there
__global__ __launch_bounds__(256) void k_row(int it) {
    if (g_flag) return;
    __shared__ float vs[2048];          // v * KK
    __shared__ float wm[8], wsum[8];
    __shared__ float erw[4];
    int t = threadIdx.x, l = t & 31, w = t >> 5;
    int g = 4095 - blockIdx.x;          // REVERSE block->row mapping
    int b = g >> 9;
    const float4* vsrc = (const float4*)(g_v + (b << 11));
    #pragma unroll
    for (int q = 0; q < 2; q++) {
        float4 v4 = vsrc[t + q * 256];
        ((float4*)vs)[t + q * 256] = make_float4(v4.x * KK, v4.y * KK, v4.z * KK, v4.w * KK);
    }
    __syncthreads();
    int row4 = (g & 511) << 2;
    int bi = (b << 11) + row4 + (w >> 1);
    int half = w & 1;
    const float* Crow = g_C + ((size_t)bi << 11) + (half << 10);
    const float* vh = vs + (half << 10);

    float4 c4[8];
    #pragma unroll
    for (int k = 0; k < 8; k++)
        c4[k] = *(const float4*)(Crow + k * 128 + l * 4);
    float x[32], mk[8];
    #pragma unroll
    for (int k = 0; k < 8; k++) {
        float4 vv = *(const float4*)(vh + k * 128 + l * 4);
        x[k * 4 + 0] = fmaf(c4[k].x, -KK, vv.x);
        x[k * 4 + 1] = fmaf(c4[k].y, -KK, vv.y);
        x[k * 4 + 2] = fmaf(c4[k].z, -KK, vv.z);
        x[k * 4 + 3] = fmaf(c4[k].w, -KK, vv.w);
        mk[k] = fmaxf(fmaxf(x[k * 4], x[k * 4 + 1]), fmaxf(x[k * 4 + 2], x[k * 4 + 3]));
    }
    float m = fmaxf(fmaxf(fmaxf(mk[0], mk[1]), fmaxf(mk[2], mk[3])),
                    fmaxf(fmaxf(mk[4], mk[5]), fmaxf(mk[6], mk[7])));
    #pragma unroll
    for (int off = 16; off; off >>= 1) m = fmaxf(m, __shfl_xor_sync(0xffffffffu, m, off));
    float s0 = 0.0f, s1 = 0.0f, s2 = 0.0f, s3 = 0.0f;
    #pragma unroll
    for (int k = 0; k < 8; k++) {
        s0 += exp2f(x[k * 4 + 0] - m);
        s1 += exp2f(x[k * 4 + 1] - m);
        s2 += exp2f(x[k * 4 + 2] - m);
        s3 += exp2f(x[k * 4 + 3] - m);
    }
    float s = (s0 + s1) + (s2 + s3);
    #pragma unroll
    for (int off = 16; off; off >>= 1) s += __shfl_xor_sync(0xffffffffu, s, off);
    if (l == 0) { wm[w] = m; wsum[w] = s; }
    __syncthreads();
    if (t < 4) {
        float M0 = wm[2 * t], M1 = wm[2 * t + 1];
        float Mn = fmaxf(M0, M1);
        float S = wsum[2 * t] * exp2f(M0 - Mn) + wsum[2 * t + 1] * exp2f(M1 - Mn);
        int bi2 = (b << 11) + row4 + t;
        float un = EPSI * g_lmu[bi2] - EL2 * (Mn + __log2f(S));
        erw[t] = fabsf(un - g_u[bi2]);
        g_u[bi2] = un;
    }
    __syncthreads();
    if (t == 0) atomicAdd(&g_errsum[it], erw[0] + erw[1] + erw[2] + erw[3]);
}

// ---- col pass partials (FORWARD sweep): (b, 128-row chunk, 256-col tile) --
__global__ __launch_bounds__(256) void k_col() {
    if (g_flag) return;
    __shared__ float us[128];           // u * KK
    int blk = blockIdx.x;               // 1024 = b(8) x chunk(16) x tile(8), fwd
    int b = blk >> 7;
    int chunk = (blk >> 3) & 15;
    int tile = blk & 7;
    int t = threadIdx.x;
    int j = (tile << 8) + t;
    int r0 = chunk << 7;
    if (t < 128) us[t] = g_u[(b << 11) + r0 + t] * KK;
    __syncthreads();
    const float* Cb = g_C + ((size_t)b << 22) + ((size_t)r0 << 11) + j;
    float m = -3.0e38f, s0 = 0.0f, s1 = 0.0f, s2 = 0.0f, s3 = 0.0f;
    #pragma unroll 1
    for (int g = 0; g < 8; g++) {
        float c[16];
        #pragma unroll
        for (int q = 0; q < 16; q++) c[q] = Cb[(size_t)q << 11];
        Cb += (size_t)16 << 11;
        float x[16];
        #pragma unroll
        for (int q = 0; q < 16; q++) x[q] = fmaf(c[q], -KK, us[g * 16 + q]);
        float m01 = fmaxf(fmaxf(x[0], x[1]), fmaxf(x[2], x[3]));
        float m23 = fmaxf(fmaxf(x[4], x[5]), fmaxf(x[6], x[7]));
        float m45 = fmaxf(fmaxf(x[8], x[9]), fmaxf(x[10], x[11]));
        float m67 = fmaxf(fmaxf(x[12], x[13]), fmaxf(x[14], x[15]));
        float lm = fmaxf(fmaxf(m01, m23), fmaxf(m45, m67));
        float mn = fmaxf(m, lm);
        float sc = exp2f(m - mn);
        s0 *= sc; s1 *= sc; s2 *= sc; s3 *= sc;
        #pragma unroll
        for (int q = 0; q < 16; q += 4) {
            s0 += exp2f(x[q + 0] - mn);
            s1 += exp2f(x[q + 1] - mn);
            s2 += exp2f(x[q + 2] - mn);
            s3 += exp2f(x[q + 3] - mn);
        }
        m = mn;
    }
    float s = (s0 + s1) + (s2 + s3);
    int pidx = (((b << 4) + chunk) << 11) + j;
    g_pm[pidx] = m;
    g_ps[pidx] = s;
}

// ---- combine col partials -> v; set early-stop flag ------------------------
__global__ __launch_bounds__(256) void k_combine(int it) {
    if (g_flag) return;
    int t = blockIdx.x * 256 + threadIdx.x;     // 16384 = b*2048 + j
    int b = t >> 11, j = t & 2047;
    float mv[16], sv[16];
    #pragma unroll
    for (int ch = 0; ch < 16; ch++) {
        mv[ch] = g_pm[(((b << 4) + ch) << 11) + j];
        sv[ch] = g_ps[(((b << 4) + ch) << 11) + j];
    }
    float M = mv[0];
    #pragma unroll
    for (int ch = 1; ch < 16; ch++) M = fmaxf(M, mv[ch]);
    float S = 0.0f;
    #pragma unroll
    for (int ch = 0; ch < 16; ch++) S += sv[ch] * exp2f(mv[ch] - M);
    g_v[t] = EPSI * g_lnu[t] - EL2 * (M + __log2f(S));
    if (t == 0) {
        // err = sum(|du|)/NB < 0.1  <=>  errsum < 0.8 (k_row fully retired)
        if (g_errsum[it] < 0.1f * NB) g_flag = 1;
    }
}

// ---- final (REVERSE sweep): out[b] = sum_ij exp((u+v-C)/eps)*C ------------
__global__ __launch_bounds__(256) void k_final(float* __restrict__ out) {
    __shared__ float vs[2048];          // v * KK
    __shared__ float srw[8];
    int t = threadIdx.x, l = t & 31, w = t >> 5;
    int g = 4095 - blockIdx.x;          // REVERSE (last col pass ended at tail)
    int b = g >> 9;
    const float4* vsrc = (const float4*)(g_v + (b << 11));
    #pragma unroll
    for (int q = 0; q < 2; q++) {
        float4 v4 = vsrc[t + q * 256];
        ((float4*)vs)[t + q * 256] = make_float4(v4.x * KK, v4.y * KK, v4.z * KK, v4.w * KK);
    }
    __syncthreads();
    int row4 = (g & 511) << 2;
    int bi = (b << 11) + row4 + (w >> 1);
    int half = w & 1;
    float uw = g_u[bi] * KK;
    const float* Crow = g_C + ((size_t)bi << 11) + (half << 10);
    const float* vh = vs + (half << 10);
    float s0 = 0.0f, s1 = 0.0f, s2 = 0.0f, s3 = 0.0f;
    #pragma unroll
    for (int k = 0; k < 8; k++) {
        float4 c = *(const float4*)(Crow + k * 128 + l * 4);
        float4 vv = *(const float4*)(vh + k * 128 + l * 4);
        s0 = fmaf(exp2f(fmaf(c.x, -KK, uw + vv.x)), c.x, s0);
        s1 = fmaf(exp2f(fmaf(c.y, -KK, uw + vv.y)), c.y, s1);
        s2 = fmaf(exp2f(fmaf(c.z, -KK, uw + vv.z)), c.z, s2);
        s3 = fmaf(exp2f(fmaf(c.w, -KK, uw + vv.w)), c.w, s3);
    }
    float s = (s0 + s1) + (s2 + s3);
    #pragma unroll
    for (int off = 16; off; off >>= 1) s += __shfl_xor_sync(0xffffffffu, s, off);
    if (l == 0) srw[w] = s;
    __syncthreads();
    if (t == 0) {
        float e = 0.0f;
        #pragma unroll
        for (int q = 0; q < 8; q++) e += srw[q];
        atomicAdd(&out[b], e);
    }
}

extern "C" void kernel_launch(void* const* d_in, const int* in_sizes, int n_in,
                              void* d_out, int out_size) {
    const float* a = (const float*)d_in[0];
    const float* b = (const float*)d_in[1];
    float* out = (float*)d_out;
    k_prep<<<64, 256>>>(a, b, out);
    dim3 gg(16, 16, NB);
    k_gemm<<<gg, 256>>>();
    k_weights<<<NB, 256>>>();
    for (int it = 0; it < 10; it++) {
        k_row<<<4096, 256>>>(it);
        k_col<<<1024, 256>>>();
        k_combine<<<64, 256>>>(it);
    }
    k_final<<<4096, 256>>>(out);
}